// round 14
// baseline (speedup 1.0000x reference)
#include <cuda_runtime.h>

// Problem constants (fixed by the dataset)
#define BB 8
#define CI 32
#define CO 64
#define FF 4
#define HH 64
#define WW 64

#define GRID 256   // one block per (b,i) plane; all co-resident (<=2 CTA/SM)

// Scratch (allocation-free rule: __device__ globals)
__device__ float g_iv[BB * CI];
__device__ float g_j0[BB * CI];
__device__ float g_j1[BB * CI];
__device__ unsigned g_arrive = 0;   // monotonic ticket counter (never reset)

// ---------------------------------------------------------------------------
// TERMINAL KERNEL (R5/R8/R13-confirmed optimum: 8.672 us, replay-floor-bound).
//
// Math: the reference collapses exactly to an affine map per (b,o):
//   out[b,o,h,w] = S0[b,o]*tc_x(w) + S1[b,o]*tc_y(h) + C[b,o]
//   S_d[b,o] = sum_{f,i} Wx[f,o,i,d] * iv[b,i]
//   C[b,o]   = sum_{f,i,d} Wy[f,o,i,d] * J_d[b,i]
//   iv/J from trapezoid quadrature over the separable uniform grid.
//
// Single kernel, 256 blocks x 256 threads.
//  Phase 1: block bi reduces plane v[bi] (4 float4 loads/thread, issued FIRST).
//  W/tc prefetch immediately after (hidden behind phase-1 consumption).
//  Grid barrier: one atomicAdd arrival per block (monotonic ticket =>
//    graph-replay-safe), poller uses plain volatile loads (no RMW).
//  Phase 2: warp w handles plane pl = bi*2 + (w>=4); 4 warps per plane
//    redundantly compute (s0,s1,c) via xor-butterfly (no smem/sync), then
//    stream 8 float4 stores each with strength-reduced addressing.
// ---------------------------------------------------------------------------
__global__ __launch_bounds__(256) void frl_fused(
    const float* __restrict__ v,  const float* __restrict__ vc,
    const float* __restrict__ tc, const float* __restrict__ Wx,
    const float* __restrict__ Wy, float* __restrict__ out)
{
    const int tid = threadIdx.x;
    const int wid = tid >> 5, lid = tid & 31;
    const int bi  = blockIdx.x;          // (b,i) plane 0..255

    __shared__ float part[3][8];

    // ---- v loads first: the longest-latency dependency on the critical path
    const float4* __restrict__ plane =
        reinterpret_cast<const float4*>(v + (size_t)bi * (HH * WW));
    const float4 t0 = plane[tid];
    const float4 t1 = plane[tid + 256];
    const float4 t2 = plane[tid + 512];
    const float4 t3 = plane[tid + 768];

    // ---- Phase-2 operand prefetch (independent; hidden behind phase 1) ----
    const int pl = bi * 2 + (wid >> 2);   // plane 0..511
    const int b  = pl >> 6;               // batch 0..7  (pl = b*64 + o)
    const int oo = pl & 63;
    float2 wxv[FF], wyv[FF];
#pragma unroll
    for (int f = 0; f < FF; ++f) {
        const int w2idx = f * (CO * CI) + oo * CI + lid;
        wxv[f] = reinterpret_cast<const float2*>(Wx)[w2idx];
        wyv[f] = reinterpret_cast<const float2*>(Wy)[w2idx];
    }
    const float tx0 = tc[0];
    const float ty0 = tc[1];
    const float dtx = tc[2] - tc[0];
    const float dty = tc[2 * WW + 1] - tc[1];

    // ================= Phase 1: weighted plane reduction ===================
    {
        float s = 0.f, sw = 0.f, sh = 0.f;
        const float4 tt[4] = { t0, t1, t2, t3 };
#pragma unroll
        for (int k = 0; k < 4; ++k) {
            const int q  = tid + k * 256;       // float4 idx 0..1023
            const int h  = q >> 4;
            const int wq = q & 15;
            const float ch = (h == 0 || h == HH - 1) ? 0.5f : 1.0f;
            const float c0 = ch * ((wq == 0)  ? 0.5f : 1.0f);
            const float c3 = ch * ((wq == 15) ? 0.5f : 1.0f);
            const float w0 = (float)(wq * 4);

            const float a0 = c0 * tt[k].x;
            const float a1 = ch * tt[k].y;
            const float a2 = ch * tt[k].z;
            const float a3 = c3 * tt[k].w;
            const float a  = a0 + a1 + a2 + a3;

            s  += a;
            sh += (float)h * a;
            sw += a0 * w0 + a1 * (w0 + 1.f) + a2 * (w0 + 2.f) + a3 * (w0 + 3.f);
        }
#pragma unroll
        for (int off = 16; off > 0; off >>= 1) {
            s  += __shfl_down_sync(0xffffffffu, s,  off);
            sw += __shfl_down_sync(0xffffffffu, sw, off);
            sh += __shfl_down_sync(0xffffffffu, sh, off);
        }
        if (lid == 0) { part[0][wid] = s; part[1][wid] = sw; part[2][wid] = sh; }
    }
    __syncthreads();

    // ---- epilogue + arrival + poll (tid 0) ----
    if (tid == 0) {
        float a = 0.f, sb = 0.f, sc = 0.f;
#pragma unroll
        for (int i = 0; i < 8; ++i) {
            a += part[0][i]; sb += part[1][i]; sc += part[2][i];
        }
        const float x0 = vc[0];
        const float y0 = vc[1];
        const float dx = vc[2] - vc[0];             // x spacing (ref's dx)
        const float dy = vc[2 * WW + 1] - vc[1];    // y spacing
        const float d2 = dx * dx;                   // ref uses dx for both
        g_iv[bi] = a * d2;
        g_j0[bi] = (x0 * a + dx * sb) * d2;
        g_j1[bi] = (y0 * a + dy * sc) * d2;
        __threadfence();                            // release g_* writes
        const unsigned ticket = atomicAdd(&g_arrive, 1u) + 1u;
        const unsigned target = ((ticket + GRID - 1u) / GRID) * GRID;
        const volatile unsigned* ctr = (const volatile unsigned*)&g_arrive;
        while (*ctr < target) { }                   // plain load poll
        __threadfence();                            // acquire
    }
    __syncthreads();

    // ================= Phase 2: combine + broadcast fill ===================
    {
        const float ivv = g_iv[b * CI + lid];
        const float j0v = g_j0[b * CI + lid];
        const float j1v = g_j1[b * CI + lid];

        float s0 = 0.f, s1 = 0.f, c = 0.f;
#pragma unroll
        for (int f = 0; f < FF; ++f) {
            s0 += wxv[f].x * ivv;
            s1 += wxv[f].y * ivv;
            c  += wyv[f].x * j0v + wyv[f].y * j1v;
        }
        // butterfly: every lane ends with the full sums
#pragma unroll
        for (int off = 16; off > 0; off >>= 1) {
            s0 += __shfl_xor_sync(0xffffffffu, s0, off);
            s1 += __shfl_xor_sync(0xffffffffu, s1, off);
            c  += __shfl_xor_sync(0xffffffffu, c,  off);
        }

        // Strength-reduced fill:
        //  thread handles q = wp*256 + k*32 + lid, k = 0..7
        //  -> wq = lid & 15 constant; h = wp*16 + 2k + (lid>>4)
        const int   wp   = wid & 3;
        const int   wq   = lid & 15;
        const int   h0   = wp * 16 + (lid >> 4);
        const float s0dx = s0 * dtx;
        const float s1dy = s1 * dty;
        const float xv0  = fmaf((float)(wq * 4), s0dx, s0 * tx0);   // x-part
        float       yp   = fmaf((float)h0, s1dy, fmaf(s1, ty0, c)); // y-part
        const float ystep = 2.0f * s1dy;

        float4* __restrict__ out4 =
            reinterpret_cast<float4*>(out) + (size_t)pl * 1024 + wp * 256 + lid;

#pragma unroll
        for (int k = 0; k < 8; ++k) {
            const float val = xv0 + yp;
            float4 r;
            r.x = val;
            r.y = val + s0dx;
            r.z = val + 2.0f * s0dx;
            r.w = val + 3.0f * s0dx;
            out4[k * 32] = r;
            yp += ystep;
        }
    }
}

extern "C" void kernel_launch(void* const* d_in, const int* in_sizes, int n_in,
                              void* d_out, int out_size)
{
    const float* v   = (const float*)d_in[0];   // [B,CI,H,W]
    const float* vc  = (const float*)d_in[1];   // [H,W,2]
    const float* tc  = (const float*)d_in[2];   // [H,W,2]
    const float* Wx  = (const float*)d_in[3];   // [F,CO,CI,2]
    const float* Wy  = (const float*)d_in[4];   // [F,CO,CI,2]
    float* out = (float*)d_out;                  // [B,CO,H,W]

    (void)in_sizes; (void)n_in; (void)out_size;

    frl_fused<<<GRID, 256>>>(v, vc, tc, Wx, Wy, out);
}